// round 1
// baseline (speedup 1.0000x reference)
#include <cuda_runtime.h>

#define WIDTH 128
#define DIMX  2
#define TT    101
#define W0F   44.0f

// Shared-memory resident network parameters (~69.5 KB -> dynamic smem).
struct Smem {
    float4 W2[WIDTH * WIDTH / 4];  // row-major [k][j], float4 over j
    float4 P1[WIDTH];              // (W1[0][k], W1[1][k], b1[k], 0)
    float4 B2[WIDTH / 4];          // b2 as float4
    float2 W3v[WIDTH];             // (W3[j][0], W3[j][1])
    float  dts[TT - 1];
    float  b3v[2];
};

// One SIREN vector-field evaluation for a single 2-D point.
// acc[128] = h1 @ W2 + b2 kept in registers; h1[k] recomputed on the fly
// (2 FMAs + 1 MUFU) so no 128-wide h1 array is needed.
__device__ __noinline__ void feval(float px, float py, const Smem* sm,
                                   float& fx, float& fy) {
    float acc[WIDTH];
#pragma unroll
    for (int j4 = 0; j4 < WIDTH / 4; j4++) {
        float4 b = sm->B2[j4];
        acc[4 * j4 + 0] = b.x;
        acc[4 * j4 + 1] = b.y;
        acc[4 * j4 + 2] = b.z;
        acc[4 * j4 + 3] = b.w;
    }
#pragma unroll 1
    for (int k = 0; k < WIDTH; k++) {
        float4 p = sm->P1[k];
        float h = __sinf(W0F * fmaf(px, p.x, fmaf(py, p.y, p.z)));
        const float4* wrow = sm->W2 + k * (WIDTH / 4);
#pragma unroll
        for (int j4 = 0; j4 < WIDTH / 4; j4++) {
            float4 w = wrow[j4];  // broadcast LDS.128 (same addr across warp)
            acc[4 * j4 + 0] = fmaf(h, w.x, acc[4 * j4 + 0]);
            acc[4 * j4 + 1] = fmaf(h, w.y, acc[4 * j4 + 1]);
            acc[4 * j4 + 2] = fmaf(h, w.z, acc[4 * j4 + 2]);
            acc[4 * j4 + 3] = fmaf(h, w.w, acc[4 * j4 + 3]);
        }
    }
    float f0 = sm->b3v[0], f1 = sm->b3v[1];
#pragma unroll
    for (int j = 0; j < WIDTH; j++) {
        float s = __sinf(W0F * acc[j]);
        float2 w3 = sm->W3v[j];
        f0 = fmaf(s, w3.x, f0);
        f1 = fmaf(s, w3.y, f1);
    }
    fx = f0;
    fy = f1;
}

extern "C" __global__ void __launch_bounds__(256, 1)
node_kernel(const float* __restrict__ t, const float* __restrict__ x0,
            const float* __restrict__ W1, const float* __restrict__ b1,
            const float* __restrict__ W2, const float* __restrict__ b2,
            const float* __restrict__ W3, const float* __restrict__ b3,
            float* __restrict__ out, int N) {
    extern __shared__ char smraw[];
    Smem* sm = reinterpret_cast<Smem*>(smraw);
    int tid = threadIdx.x;

    // Cooperative parameter staging into shared memory.
    for (int i = tid; i < WIDTH * WIDTH / 4; i += blockDim.x)
        sm->W2[i] = reinterpret_cast<const float4*>(W2)[i];
    for (int k = tid; k < WIDTH; k += blockDim.x) {
        sm->P1[k]  = make_float4(W1[k], W1[WIDTH + k], b1[k], 0.0f);
        sm->W3v[k] = reinterpret_cast<const float2*>(W3)[k];
    }
    for (int i = tid; i < WIDTH / 4; i += blockDim.x)
        sm->B2[i] = reinterpret_cast<const float4*>(b2)[i];
    for (int s = tid; s < TT - 1; s += blockDim.x)
        sm->dts[s] = t[s + 1] - t[s];
    if (tid < 2) sm->b3v[tid] = b3[tid];
    __syncthreads();

    int i = blockIdx.x * blockDim.x + tid;
    if (i >= N) return;

    float2 y = reinterpret_cast<const float2*>(x0)[i];
    float2* outv = reinterpret_cast<float2*>(out);
    outv[i] = y;  // t = 0 row

    const float third = 1.0f / 3.0f;
#pragma unroll 1
    for (int s = 0; s < TT - 1; s++) {
        float dt = sm->dts[s];
        float k1x, k1y, k2x, k2y, k3x, k3y, k4x, k4y;
        // torchdiffeq rk4_alt (3/8-rule)
        feval(y.x, y.y, sm, k1x, k1y);
        feval(y.x + dt * k1x * third, y.y + dt * k1y * third, sm, k2x, k2y);
        feval(y.x + dt * (k2x - k1x * third), y.y + dt * (k2y - k1y * third),
              sm, k3x, k3y);
        feval(y.x + dt * (k1x - k2x + k3x), y.y + dt * (k1y - k2y + k3y),
              sm, k4x, k4y);
        y.x = y.x + (k1x + 3.0f * (k2x + k3x) + k4x) * dt * 0.125f;
        y.y = y.y + (k1y + 3.0f * (k2y + k3y) + k4y) * dt * 0.125f;
        outv[(size_t)(s + 1) * N + i] = y;
    }
}

extern "C" void kernel_launch(void* const* d_in, const int* in_sizes, int n_in,
                              void* d_out, int out_size) {
    const float* t  = (const float*)d_in[0];
    const float* x0 = (const float*)d_in[1];
    const float* W1 = (const float*)d_in[2];
    const float* b1 = (const float*)d_in[3];
    const float* W2 = (const float*)d_in[4];
    const float* b2 = (const float*)d_in[5];
    const float* W3 = (const float*)d_in[6];
    const float* b3 = (const float*)d_in[7];
    int N = in_sizes[1] / 2;

    int smem = (int)sizeof(Smem);
    cudaFuncSetAttribute(node_kernel,
                         cudaFuncAttributeMaxDynamicSharedMemorySize, smem);
    node_kernel<<<(N + 255) / 256, 256, smem>>>(t, x0, W1, b1, W2, b2, W3, b3,
                                                (float*)d_out, N);
}

// round 8
// speedup vs baseline: 9.7088x; 9.7088x over previous
#include <cuda_runtime.h>
#include <cstdint>

#define TT    101
#define W0F   44.0f
#define NTHR  256

// ---- dynamic smem layout (bytes) ----
#define BH_OFF    0                   // W2 tf32-grid pairs [kt][n][tig]: 64 KB
#define P1_OFF    65536               // float4[128]: (44*W1x, 44*W1y, 44*b1, 0)
#define WB_OFF    (P1_OFF + 2048)     // float4[128]: (W3x, W3y, 44*b2, 0)
#define DTS_OFF   (WB_OFF + 2048)     // float[100]
#define B3_OFF    (DTS_OFF + 512)     // float[2]
#define SMEM_TOTAL (B3_OFF + 16)

// Round-to-nearest onto the tf32 grid via integer ops (cannot be elided or
// folded; unbiased whether or not the MMA hardware truncates internally).
static __device__ __forceinline__ uint32_t tf32rn(float x) {
    uint32_t u = __float_as_uint(x);
    u += 0x1000u + ((u >> 13) & 1u);
    return u & 0xFFFFE000u;
}

static __device__ __forceinline__ void mma8(float* d, const uint32_t* a,
                                            uint32_t b0, uint32_t b1) {
    asm volatile(
        "mma.sync.aligned.m16n8k8.row.col.f32.tf32.tf32.f32 "
        "{%0,%1,%2,%3}, {%4,%5,%6,%7}, {%8,%9}, {%0,%1,%2,%3};"
        : "+f"(d[0]), "+f"(d[1]), "+f"(d[2]), "+f"(d[3])
        : "r"(a[0]), "r"(a[1]), "r"(a[2]), "r"(a[3]), "r"(b0), "r"(b1));
}

// One SIREN vector-field eval for this warp's 32 points (lane l owns point l).
// Single-pass tf32 MMA; A fragments computed in registers (each h1 element is
// consumed by exactly one lane, which shfl's the owning point's coords).
__device__ __noinline__ void feval(float px, float py, const char* sm,
                                   int lane, float b3x, float b3y,
                                   float& fx, float& fy) {
    const int g = lane >> 2, tig = lane & 3;

    // coords of the 4 rows (8j+g) whose fragment slots this lane owns
    float rx[4], ry[4];
#pragma unroll
    for (int j = 0; j < 4; j++) {
        rx[j] = __shfl_sync(0xffffffffu, px, 8 * j + g);
        ry[j] = __shfl_sync(0xffffffffu, py, 8 * j + g);
    }

    float acc[128];
#pragma unroll
    for (int i = 0; i < 128; i++) acc[i] = 0.0f;

    const float4* P1 = reinterpret_cast<const float4*>(sm + P1_OFF);
    const uint2* BH = reinterpret_cast<const uint2*>(sm + BH_OFF);

#pragma unroll 1
    for (int kt = 0; kt < 16; kt++) {
        const int c0 = 8 * kt + tig;
        float4 q0 = P1[c0], q1 = P1[c0 + 4];

        // h1 fragment for cols c0, c0+4, rows 8j+g (rounded to tf32 grid)
        uint32_t ah[8];
#pragma unroll
        for (int j = 0; j < 4; j++) {
            float h0 = __sinf(fmaf(rx[j], q0.x, fmaf(ry[j], q0.y, q0.z)));
            float h1 = __sinf(fmaf(rx[j], q1.x, fmaf(ry[j], q1.y, q1.z)));
            const int base = 4 * (j >> 1) + (j & 1);  // m-tile j>>1, row-slot j&1
            ah[base]     = tf32rn(h0);
            ah[base + 2] = tf32rn(h1);
        }

        const uint2* BHk = BH + kt * 512;
#pragma unroll
        for (int nt = 0; nt < 16; nt++) {
            uint2 bh = BHk[(8 * nt + g) * 4 + tig];
            mma8(acc + nt * 4, ah, bh.x, bh.y);
            mma8(acc + 64 + nt * 4, ah + 4, bh.x, bh.y);
        }
    }

    // ---- layer 3: f = sin(44*D + 44*b2) @ W3 + b3 ----
    const float4* WB = reinterpret_cast<const float4*>(sm + WB_OFF);
    float ps[8];
#pragma unroll
    for (int i = 0; i < 8; i++) ps[i] = 0.0f;
#pragma unroll
    for (int m = 0; m < 2; m++) {
#pragma unroll
        for (int nt = 0; nt < 16; nt++) {
            float4 w0 = WB[8 * nt + 2 * tig];
            float4 w1 = WB[8 * nt + 2 * tig + 1];
            const float* d = acc + m * 64 + nt * 4;
            float h00 = __sinf(fmaf(W0F, d[0], w0.z));  // row g,   col 2tig
            float h01 = __sinf(fmaf(W0F, d[1], w1.z));  // row g,   col 2tig+1
            float h10 = __sinf(fmaf(W0F, d[2], w0.z));  // row g+8
            float h11 = __sinf(fmaf(W0F, d[3], w1.z));
            ps[m * 4 + 0] = fmaf(h00, w0.x, fmaf(h01, w1.x, ps[m * 4 + 0]));
            ps[m * 4 + 1] = fmaf(h00, w0.y, fmaf(h01, w1.y, ps[m * 4 + 1]));
            ps[m * 4 + 2] = fmaf(h10, w0.x, fmaf(h11, w1.x, ps[m * 4 + 2]));
            ps[m * 4 + 3] = fmaf(h10, w0.y, fmaf(h11, w1.y, ps[m * 4 + 3]));
        }
    }
    // reduce across the 4 lanes of each thread-group (lane bits 0,1)
#pragma unroll
    for (int d = 1; d <= 2; d <<= 1)
#pragma unroll
        for (int i = 0; i < 8; i++)
            ps[i] += __shfl_xor_sync(0xffffffffu, ps[i], d);

    // route row r = 8*s + g back to owner lane r (src lane = (r&7)*4);
    // ps index = 2*s + comp where s = 2m+h, row = 8s+g
    const int src = (lane & 7) * 4;
    float rx0 = __shfl_sync(0xffffffffu, ps[0], src);
    float ry0 = __shfl_sync(0xffffffffu, ps[1], src);
    float rx1 = __shfl_sync(0xffffffffu, ps[2], src);
    float ry1 = __shfl_sync(0xffffffffu, ps[3], src);
    float rx2 = __shfl_sync(0xffffffffu, ps[4], src);
    float ry2 = __shfl_sync(0xffffffffu, ps[5], src);
    float rx3 = __shfl_sync(0xffffffffu, ps[6], src);
    float ry3 = __shfl_sync(0xffffffffu, ps[7], src);
    const int s = lane >> 3;
    // + b3 (the R4-R6 bug: this term was staged but never added)
    fx = b3x + ((s == 0) ? rx0 : (s == 1) ? rx1 : (s == 2) ? rx2 : rx3);
    fy = b3y + ((s == 0) ? ry0 : (s == 1) ? ry1 : (s == 2) ? ry2 : ry3);
}

extern "C" __global__ void __launch_bounds__(NTHR, 1)
node_hmma(const float* __restrict__ t, const float* __restrict__ x0,
          const float* __restrict__ W1, const float* __restrict__ b1,
          const float* __restrict__ W2, const float* __restrict__ b2,
          const float* __restrict__ W3, const float* __restrict__ b3g,
          float* __restrict__ out, int N) {
    extern __shared__ char sm[];
    const int tid = threadIdx.x;
    const int lane = tid & 31;

    // ---- stage W2 as tf32-grid lds.64 pairs: [kt][n][tig] ----
    for (int idx = tid; idx < 16 * 128 * 4; idx += NTHR) {
        int kt = idx >> 9, rest = idx & 511;
        int n = rest >> 2, tg = rest & 3;
        int k0 = kt * 8 + tg;
        uint2 pr;
        pr.x = tf32rn(W2[k0 * 128 + n]);
        pr.y = tf32rn(W2[(k0 + 4) * 128 + n]);
        reinterpret_cast<uint2*>(sm + BH_OFF)[idx] = pr;
    }
    for (int k = tid; k < 128; k += NTHR) {
        reinterpret_cast<float4*>(sm + P1_OFF)[k] =
            make_float4(W0F * W1[k], W0F * W1[128 + k], W0F * b1[k], 0.0f);
        reinterpret_cast<float4*>(sm + WB_OFF)[k] =
            make_float4(W3[2 * k], W3[2 * k + 1], W0F * b2[k], 0.0f);
    }
    for (int s = tid; s < TT - 1; s += NTHR)
        reinterpret_cast<float*>(sm + DTS_OFF)[s] = t[s + 1] - t[s];
    if (tid < 2) reinterpret_cast<float*>(sm + B3_OFF)[tid] = b3g[tid];
    __syncthreads();  // only CTA-wide sync; warps independent afterwards

    const float b3x = reinterpret_cast<const float*>(sm + B3_OFF)[0];
    const float b3y = reinterpret_cast<const float*>(sm + B3_OFF)[1];

    const int gid = blockIdx.x * NTHR + tid;
    const bool live = gid < N;
    float2 y = live ? reinterpret_cast<const float2*>(x0)[gid]
                    : make_float2(0.0f, 0.0f);
    float2* outv = reinterpret_cast<float2*>(out);
    if (live) outv[gid] = y;  // t = 0 row

    const float third = 1.0f / 3.0f;
#pragma unroll 1
    for (int s = 0; s < TT - 1; s++) {
        float dt = reinterpret_cast<const float*>(sm + DTS_OFF)[s];
        float k1x, k1y, k2x, k2y, k3x, k3y, k4x, k4y;
        // torchdiffeq rk4_alt (3/8-rule)
        feval(y.x, y.y, sm, lane, b3x, b3y, k1x, k1y);
        feval(y.x + dt * k1x * third, y.y + dt * k1y * third,
              sm, lane, b3x, b3y, k2x, k2y);
        feval(y.x + dt * (k2x - k1x * third), y.y + dt * (k2y - k1y * third),
              sm, lane, b3x, b3y, k3x, k3y);
        feval(y.x + dt * (k1x - k2x + k3x), y.y + dt * (k1y - k2y + k3y),
              sm, lane, b3x, b3y, k4x, k4y);
        y.x = y.x + (k1x + 3.0f * (k2x + k3x) + k4x) * dt * 0.125f;
        y.y = y.y + (k1y + 3.0f * (k2y + k3y) + k4y) * dt * 0.125f;
        if (live) outv[(size_t)(s + 1) * N + gid] = y;
    }
}

extern "C" void kernel_launch(void* const* d_in, const int* in_sizes, int n_in,
                              void* d_out, int out_size) {
    const float* t  = (const float*)d_in[0];
    const float* x0 = (const float*)d_in[1];
    const float* W1 = (const float*)d_in[2];
    const float* b1 = (const float*)d_in[3];
    const float* W2 = (const float*)d_in[4];
    const float* b2 = (const float*)d_in[5];
    const float* W3 = (const float*)d_in[6];
    const float* b3 = (const float*)d_in[7];
    int N = in_sizes[1] / 2;

    cudaFuncSetAttribute(node_hmma,
                         cudaFuncAttributeMaxDynamicSharedMemorySize, SMEM_TOTAL);
    int grid = (N + NTHR - 1) / NTHR;
    node_hmma<<<grid, NTHR, SMEM_TOTAL>>>(t, x0, W1, b1, W2, b2, W3, b3,
                                          (float*)d_out, N);
}

// round 9
// speedup vs baseline: 18.5604x; 1.9117x over previous
#include <cuda_runtime.h>
#include <cstdint>

#define TT    101
#define W0F   44.0f
#define NTHR  256

// ---- dynamic smem layout (bytes) ----
#define BF_OFF    0                   // W2 f16 fragments [kt][ntp][g][tig] uint4: 32 KB
#define P1_OFF    32768               // float4[128]: (44*W1x, 44*W1y, 44*b1, 0)
#define WB_OFF    (P1_OFF + 2048)     // float4[128]: (W3x, W3y, 44*b2, 0)
#define DTS_OFF   (WB_OFF + 2048)     // float[100]
#define B3_OFF    (DTS_OFF + 512)     // float[2]
#define SMEM_TOTAL (B3_OFF + 16)

// pack two f32 -> f16x2, first arg in the LOW half (k-index 2tig)
static __device__ __forceinline__ uint32_t h2(float lo, float hi) {
    uint32_t r;
    asm("cvt.rn.f16x2.f32 %0, %1, %2;" : "=r"(r) : "f"(hi), "f"(lo));
    return r;
}

static __device__ __forceinline__ void mma16(float* d, const uint32_t* a,
                                             uint32_t b0, uint32_t b1) {
    asm volatile(
        "mma.sync.aligned.m16n8k16.row.col.f32.f16.f16.f32 "
        "{%0,%1,%2,%3}, {%4,%5,%6,%7}, {%8,%9}, {%0,%1,%2,%3};"
        : "+f"(d[0]), "+f"(d[1]), "+f"(d[2]), "+f"(d[3])
        : "r"(a[0]), "r"(a[1]), "r"(a[2]), "r"(a[3]), "r"(b0), "r"(b1));
}

// One SIREN vector-field eval for this warp's 32 points (lane l owns point l).
// fp16 m16n8k16 MMAs (11-bit mantissa = tf32 precision, fp32 accumulate),
// 256 MMAs per eval. A fragments computed in registers per k-chunk.
__device__ __noinline__ void feval(float px, float py, const char* sm,
                                   int lane, float b3x, float b3y,
                                   float& fx, float& fy) {
    const int g = lane >> 2, tig = lane & 3;

    // coords of the 4 rows (8j+g) whose fragment slots this lane owns
    float rx[4], ry[4];
#pragma unroll
    for (int j = 0; j < 4; j++) {
        rx[j] = __shfl_sync(0xffffffffu, px, 8 * j + g);
        ry[j] = __shfl_sync(0xffffffffu, py, 8 * j + g);
    }

    float acc[128];
#pragma unroll
    for (int i = 0; i < 128; i++) acc[i] = 0.0f;

    const float4* P1 = reinterpret_cast<const float4*>(sm + P1_OFF);
    const uint4* BF = reinterpret_cast<const uint4*>(sm + BF_OFF);

#pragma unroll
    for (int kt = 0; kt < 8; kt++) {
        const int c0 = 16 * kt + 2 * tig;
        float4 pA = P1[c0], pB = P1[c0 + 1], pC = P1[c0 + 8], pD = P1[c0 + 9];

        // A fragments: ah[m] = {a0,a1,a2,a3} for rows {16m+g, 16m+8+g},
        // cols {c0, c0+1} (a0/a1) and {c0+8, c0+9} (a2/a3)
        uint32_t ah[2][4];
#pragma unroll
        for (int j = 0; j < 4; j++) {
            float sA = __sinf(fmaf(rx[j], pA.x, fmaf(ry[j], pA.y, pA.z)));
            float sB = __sinf(fmaf(rx[j], pB.x, fmaf(ry[j], pB.y, pB.z)));
            float sC = __sinf(fmaf(rx[j], pC.x, fmaf(ry[j], pC.y, pC.z)));
            float sD = __sinf(fmaf(rx[j], pD.x, fmaf(ry[j], pD.y, pD.z)));
            const int m = j >> 1, rs = j & 1;
            ah[m][rs]     = h2(sA, sB);
            ah[m][rs + 2] = h2(sC, sD);
        }

        const uint4* Bk = BF + kt * 256;
#pragma unroll
        for (int ntp = 0; ntp < 8; ntp++) {
            uint4 b = Bk[ntp * 32 + g * 4 + tig];
            mma16(acc + (2 * ntp) * 4,          ah[0], b.x, b.y);
            mma16(acc + 64 + (2 * ntp) * 4,     ah[1], b.x, b.y);
            mma16(acc + (2 * ntp + 1) * 4,      ah[0], b.z, b.w);
            mma16(acc + 64 + (2 * ntp + 1) * 4, ah[1], b.z, b.w);
        }
    }

    // ---- layer 3: f = sin(44*D + 44*b2) @ W3 + b3 ----
    const float4* WB = reinterpret_cast<const float4*>(sm + WB_OFF);
    float ps[8];
#pragma unroll
    for (int i = 0; i < 8; i++) ps[i] = 0.0f;
#pragma unroll
    for (int m = 0; m < 2; m++) {
#pragma unroll
        for (int nt = 0; nt < 16; nt++) {
            float4 w0 = WB[8 * nt + 2 * tig];
            float4 w1 = WB[8 * nt + 2 * tig + 1];
            const float* d = acc + m * 64 + nt * 4;
            float h00 = __sinf(fmaf(W0F, d[0], w0.z));  // row g,   col 2tig
            float h01 = __sinf(fmaf(W0F, d[1], w1.z));  // row g,   col 2tig+1
            float h10 = __sinf(fmaf(W0F, d[2], w0.z));  // row g+8
            float h11 = __sinf(fmaf(W0F, d[3], w1.z));
            ps[m * 4 + 0] = fmaf(h00, w0.x, fmaf(h01, w1.x, ps[m * 4 + 0]));
            ps[m * 4 + 1] = fmaf(h00, w0.y, fmaf(h01, w1.y, ps[m * 4 + 1]));
            ps[m * 4 + 2] = fmaf(h10, w0.x, fmaf(h11, w1.x, ps[m * 4 + 2]));
            ps[m * 4 + 3] = fmaf(h10, w0.y, fmaf(h11, w1.y, ps[m * 4 + 3]));
        }
    }
    // reduce across the 4 lanes of each thread-group (lane bits 0,1)
#pragma unroll
    for (int d = 1; d <= 2; d <<= 1)
#pragma unroll
        for (int i = 0; i < 8; i++)
            ps[i] += __shfl_xor_sync(0xffffffffu, ps[i], d);

    // route row r = 8*s + g back to owner lane r (src lane = (r&7)*4);
    // ps index = 2*s + comp where s = 2m+h, row = 8s+g
    const int src = (lane & 7) * 4;
    float rx0 = __shfl_sync(0xffffffffu, ps[0], src);
    float ry0 = __shfl_sync(0xffffffffu, ps[1], src);
    float rx1 = __shfl_sync(0xffffffffu, ps[2], src);
    float ry1 = __shfl_sync(0xffffffffu, ps[3], src);
    float rx2 = __shfl_sync(0xffffffffu, ps[4], src);
    float ry2 = __shfl_sync(0xffffffffu, ps[5], src);
    float rx3 = __shfl_sync(0xffffffffu, ps[6], src);
    float ry3 = __shfl_sync(0xffffffffu, ps[7], src);
    const int s = lane >> 3;
    fx = b3x + ((s == 0) ? rx0 : (s == 1) ? rx1 : (s == 2) ? rx2 : rx3);
    fy = b3y + ((s == 0) ? ry0 : (s == 1) ? ry1 : (s == 2) ? ry2 : ry3);
}

extern "C" __global__ void __launch_bounds__(NTHR, 1)
node_hmma(const float* __restrict__ t, const float* __restrict__ x0,
          const float* __restrict__ W1, const float* __restrict__ b1,
          const float* __restrict__ W2, const float* __restrict__ b2,
          const float* __restrict__ W3, const float* __restrict__ b3g,
          float* __restrict__ out, int N) {
    extern __shared__ char sm[];
    const int tid = threadIdx.x;
    const int lane = tid & 31;

    // ---- stage W2 as f16 fragment uint4s: [kt][ntp][g][tig] ----
    // .x = B-frag b0 for n=16ntp+g   (k rows k0, k0+1)
    // .y = b1 for same n             (k rows k0+8, k0+9)
    // .z/.w = same for n+8
    for (int idx = tid; idx < 8 * 8 * 32; idx += NTHR) {
        int tg = idx & 3, g = (idx >> 2) & 7, ntp = (idx >> 5) & 7, kt = idx >> 8;
        int n0 = 16 * ntp + g, n1 = n0 + 8;
        int k0 = 16 * kt + 2 * tg;
        uint4 v;
        v.x = h2(W2[k0 * 128 + n0],       W2[(k0 + 1) * 128 + n0]);
        v.y = h2(W2[(k0 + 8) * 128 + n0], W2[(k0 + 9) * 128 + n0]);
        v.z = h2(W2[k0 * 128 + n1],       W2[(k0 + 1) * 128 + n1]);
        v.w = h2(W2[(k0 + 8) * 128 + n1], W2[(k0 + 9) * 128 + n1]);
        reinterpret_cast<uint4*>(sm + BF_OFF)[idx] = v;
    }
    for (int k = tid; k < 128; k += NTHR) {
        reinterpret_cast<float4*>(sm + P1_OFF)[k] =
            make_float4(W0F * W1[k], W0F * W1[128 + k], W0F * b1[k], 0.0f);
        reinterpret_cast<float4*>(sm + WB_OFF)[k] =
            make_float4(W3[2 * k], W3[2 * k + 1], W0F * b2[k], 0.0f);
    }
    for (int s = tid; s < TT - 1; s += NTHR)
        reinterpret_cast<float*>(sm + DTS_OFF)[s] = t[s + 1] - t[s];
    if (tid < 2) reinterpret_cast<float*>(sm + B3_OFF)[tid] = b3g[tid];
    __syncthreads();  // only CTA-wide sync; warps independent afterwards

    const float b3x = reinterpret_cast<const float*>(sm + B3_OFF)[0];
    const float b3y = reinterpret_cast<const float*>(sm + B3_OFF)[1];

    const int gid = blockIdx.x * NTHR + tid;
    const bool live = gid < N;
    float2 y = live ? reinterpret_cast<const float2*>(x0)[gid]
                    : make_float2(0.0f, 0.0f);
    float2* outv = reinterpret_cast<float2*>(out);
    if (live) outv[gid] = y;  // t = 0 row

    const float third = 1.0f / 3.0f;
#pragma unroll 1
    for (int s = 0; s < TT - 1; s++) {
        float dt = reinterpret_cast<const float*>(sm + DTS_OFF)[s];
        float k1x, k1y, k2x, k2y, k3x, k3y, k4x, k4y;
        // torchdiffeq rk4_alt (3/8-rule)
        feval(y.x, y.y, sm, lane, b3x, b3y, k1x, k1y);
        feval(y.x + dt * k1x * third, y.y + dt * k1y * third,
              sm, lane, b3x, b3y, k2x, k2y);
        feval(y.x + dt * (k2x - k1x * third), y.y + dt * (k2y - k1y * third),
              sm, lane, b3x, b3y, k3x, k3y);
        feval(y.x + dt * (k1x - k2x + k3x), y.y + dt * (k1y - k2y + k3y),
              sm, lane, b3x, b3y, k4x, k4y);
        y.x = y.x + (k1x + 3.0f * (k2x + k3x) + k4x) * dt * 0.125f;
        y.y = y.y + (k1y + 3.0f * (k2y + k3y) + k4y) * dt * 0.125f;
        if (live) outv[(size_t)(s + 1) * N + gid] = y;
    }
}

extern "C" void kernel_launch(void* const* d_in, const int* in_sizes, int n_in,
                              void* d_out, int out_size) {
    const float* t  = (const float*)d_in[0];
    const float* x0 = (const float*)d_in[1];
    const float* W1 = (const float*)d_in[2];
    const float* b1 = (const float*)d_in[3];
    const float* W2 = (const float*)d_in[4];
    const float* b2 = (const float*)d_in[5];
    const float* W3 = (const float*)d_in[6];
    const float* b3 = (const float*)d_in[7];
    int N = in_sizes[1] / 2;

    cudaFuncSetAttribute(node_hmma,
                         cudaFuncAttributeMaxDynamicSharedMemorySize, SMEM_TOTAL);
    int grid = (N + NTHR - 1) / NTHR;
    node_hmma<<<grid, NTHR, SMEM_TOTAL>>>(t, x0, W1, b1, W2, b2, W3, b3,
                                          (float*)d_out, N);
}